// round 14
// baseline (speedup 1.0000x reference)
#include <cuda_runtime.h>
#include <cuda_bf16.h>

// PPO loss, persistent-CTA software pipeline.
// Grid = 148 SMs x 8 CTAs = 1184 persistent blocks; each loops over chunks
// (chunk += gridDim). Per iteration, after the recompute (last use of r/v regs)
// we issue the NEXT chunk's r/v float4 loads into the same registers and the L2
// prefetch of the next chunk's probs — that DRAM traffic overlaps the current
// chunk's probs pass (L2-hit from the previous iteration's prefetch) and
// reductions. Zero extra registers; no cross-block sync.
// Reverse recurrences are local (0.99^512 truncation ~3e-6 rel): 512-elem halo.

#define PPO_EPS    0.2f
#define PPO_GAMMA  0.99f
#define PPO_A1     (0.99f * 0.95f)   // gamma * lambda
#define PPO_C1     0.5f
#define PPO_C2     0.01f

#define THREADS    128
#define NWARP      4
#define SEG        20                      // elements per thread (80B, float4-aligned)
#define OUT_CHUNK  2048                    // outputs per chunk (halo = 512)
#define GRID_MAX   1184                    // 148 SMs x 8 resident CTAs

// advantages in padded layout pi(i)=i+i/SEG (stride-21 per thread, conflict-free)
#define ADV_WORDS  2160                    // > pi(OUT_CHUNK-1) = 2149

__device__ float g_partials[2048];
__device__ unsigned int g_count = 0;

__host__ __device__ constexpr double dpow(double b, int n) {
    double r = 1.0;
    for (int i = 0; i < n; ++i) r *= b;
    return r;
}
#define FG0  ((float)dpow((double)PPO_A1,    SEG))       // a1^20
#define FV0  ((float)dpow((double)PPO_GAMMA, SEG))       // g^20
#define CG(k) ((float)dpow((double)PPO_A1,    SEG << (k)))
#define CV(k) ((float)dpow((double)PPO_GAMMA, SEG << (k)))
#define FWG0 ((float)dpow((double)PPO_A1,    SEG * 32))  // a1^640
#define FWV0 ((float)dpow((double)PPO_GAMMA, SEG * 32))  // g^640

// Load one chunk's per-thread segment (SEG r, SEG v, 1 lookahead v) to registers.
__device__ __forceinline__ void load_seg(const float* __restrict__ rewards,
                                         const float* __restrict__ values,
                                         int gbase, int T,
                                         float* r, float* v, float& vNext)
{
    if (gbase + SEG < T) {
        #pragma unroll
        for (int k = 0; k < SEG / 4; ++k) {
            float4 r4 = *reinterpret_cast<const float4*>(rewards + gbase + 4 * k);
            float4 v4 = *reinterpret_cast<const float4*>(values  + gbase + 4 * k);
            r[4*k+0] = r4.x; r[4*k+1] = r4.y; r[4*k+2] = r4.z; r[4*k+3] = r4.w;
            v[4*k+0] = v4.x; v[4*k+1] = v4.y; v[4*k+2] = v4.z; v[4*k+3] = v4.w;
        }
        vNext = values[gbase + SEG];
    } else {
        #pragma unroll
        for (int i = 0; i < SEG; ++i) {
            bool ok = gbase + i < T;
            r[i] = ok ? rewards[gbase + i] : 0.0f;
            v[i] = ok ? values[gbase + i]  : 0.0f;
        }
        vNext = 0.0f;
    }
}

__device__ __forceinline__ void prefetch_probs(const float* __restrict__ probs,
                                               const float* __restrict__ probs_old,
                                               int s, int tid)
{
    // 128 threads x 128B lines = 16KB = both 8KB arrays exactly.
    const char* base = (tid < 64)
        ? (const char*)(probs + s)     + (size_t)tid * 128
        : (const char*)(probs_old + s) + (size_t)(tid - 64) * 128;
    asm volatile("prefetch.global.L2 [%0];" :: "l"(base));
}

__global__ __launch_bounds__(THREADS, 8)
void ppo_fused(const float* __restrict__ probs,
               const float* __restrict__ probs_old,
               const float* __restrict__ rewards,
               const float* __restrict__ values,
               float* __restrict__ out,
               int T, int nchunks)
{
    __shared__ float adv[ADV_WORDS];
    __shared__ float wtg[NWARP], wtv[NWARP];   // warp totals
    __shared__ float wcg[NWARP], wcv[NWARP];   // warp carries
    __shared__ unsigned int s_last;

    const int tid  = threadIdx.x;
    const int lane = tid & 31;
    const int w    = tid >> 5;
    const int gridN = gridDim.x;

    // Per-lane / per-warp carry factors (loop-invariant)
    float facg = 1.0f, facv = 1.0f;
    {
        int m = 31 - lane;
        if (m & 1)  { facg *= CG(0); facv *= CV(0); }
        if (m & 2)  { facg *= CG(1); facv *= CV(1); }
        if (m & 4)  { facg *= CG(2); facv *= CV(2); }
        if (m & 8)  { facg *= CG(3); facv *= CV(3); }
        if (m & 16) { facg *= CG(4); facv *= CV(4); }
    }

    float accClip = 0.0f, accVl = 0.0f, accEnt = 0.0f;
    float r[SEG], v[SEG], vNext = 0.0f;

    int chunk = blockIdx.x;
    if (chunk < nchunks) {   // prologue: first chunk's loads + prefetch
        load_seg(rewards, values, chunk * OUT_CHUNK + tid * SEG, T, r, v, vNext);
        if (chunk * OUT_CHUNK + OUT_CHUNK <= T)
            prefetch_probs(probs, probs_old, chunk * OUT_CHUNK, tid);
    }

    for (; chunk < nchunks; chunk += gridN) {
        const int s = chunk * OUT_CHUNK;
        const bool full = s + OUT_CHUNK <= T;

        // ---- Per-thread reverse aggregates ----
        float Lg = 0.0f, Lv = 0.0f;
        {
            float vn = vNext;
            #pragma unroll
            for (int i = SEG - 1; i >= 0; --i) {
                float delta = r[i] - v[i] + PPO_GAMMA * vn;
                Lg = fmaf(PPO_A1,    Lg, delta);
                Lv = fmaf(PPO_GAMMA, Lv, r[i]);
                vn = v[i];
            }
        }

        // ---- Warp-level reverse inclusive scan ----
        float Sg = Lg, Sv = Lv, Fg = FG0, Fv = FV0;
        #pragma unroll
        for (int off = 1; off < 32; off <<= 1) {
            float og = __shfl_down_sync(0xffffffffu, Sg, off);
            float ov = __shfl_down_sync(0xffffffffu, Sv, off);
            if (lane + off < 32) { Sg = fmaf(Fg, og, Sg); Sv = fmaf(Fv, ov, Sv); }
            Fg *= Fg; Fv *= Fv;
        }
        float eg = __shfl_down_sync(0xffffffffu, Sg, 1);
        float ev = __shfl_down_sync(0xffffffffu, Sv, 1);
        if (lane == 31) { eg = 0.0f; ev = 0.0f; }
        if (lane == 0) { wtg[w] = Sg; wtv[w] = Sv; }
        __syncthreads();

        // ---- Warp 0 scans warp totals ----
        if (w == 0) {
            float tg = (lane < NWARP) ? wtg[lane] : 0.0f;
            float tv = (lane < NWARP) ? wtv[lane] : 0.0f;
            float FWg = FWG0, FWv = FWV0;
            #pragma unroll
            for (int off = 1; off < NWARP; off <<= 1) {
                float og = __shfl_down_sync(0xffffffffu, tg, off);
                float ov = __shfl_down_sync(0xffffffffu, tv, off);
                if (lane + off < NWARP) { tg = fmaf(FWg, og, tg); tv = fmaf(FWv, ov, tv); }
                FWg *= FWg; FWv *= FWv;
            }
            float cg = __shfl_down_sync(0xffffffffu, tg, 1);
            float cv = __shfl_down_sync(0xffffffffu, tv, 1);
            if (lane == NWARP - 1) { cg = 0.0f; cv = 0.0f; }
            if (lane < NWARP) { wcg[lane] = cg; wcv[lane] = cv; }
        }
        __syncthreads();

        float Eg = fmaf(facg, wcg[w], eg);
        float Ev = fmaf(facv, wcv[w], ev);

        // ---- Recompute with carry (LAST use of r/v): vl + adv -> SMEM ----
        const int baseL = tid * SEG;
        const int baseP = baseL + tid;   // 21*tid
        {
            float g = Eg, V = Ev, vn = vNext;
            #pragma unroll
            for (int i = SEG - 1; i >= 0; --i) {
                float delta = r[i] - v[i] + PPO_GAMMA * vn;
                g = fmaf(PPO_A1,    g, delta);
                V = fmaf(PPO_GAMMA, V, r[i]);
                vn = v[i];
                if (baseL + i < OUT_CHUNK) {
                    float d = v[i] - V;
                    accVl = fmaf(d, d, accVl);
                    adv[baseP + i] = g;
                }
            }
        }

        // ---- Pipeline: issue NEXT chunk's r/v loads + probs prefetch now ----
        const int nchunk = chunk + gridN;
        if (nchunk < nchunks) {
            load_seg(rewards, values, nchunk * OUT_CHUNK + tid * SEG, T, r, v, vNext);
            if (nchunk * OUT_CHUNK + OUT_CHUNK <= T)
                prefetch_probs(probs, probs_old, nchunk * OUT_CHUNK, tid);
        }
        __syncthreads();   // adv visible

        // ---- Probs pass for CURRENT chunk (L2-hit from last prefetch) ----
        if (full) {
            const float4* p4p  = reinterpret_cast<const float4*>(probs + s);
            const float4* po4p = reinterpret_cast<const float4*>(probs_old + s);
            #pragma unroll
            for (int it = 0; it < OUT_CHUNK / (4 * THREADS); ++it) {   // 4 iters
                int k = tid + it * THREADS;
                float4 p4 = p4p[k];
                float4 o4 = po4p[k];
                float pv[4] = {p4.x, p4.y, p4.z, p4.w};
                float ov[4] = {o4.x, o4.y, o4.z, o4.w};
                int li = 4 * k;
                #pragma unroll
                for (int c = 0; c < 4; ++c) {
                    int j = li + c;
                    float a = adv[j + j / SEG];
                    float ratio = __fdividef(pv[c], ov[c]);
                    float cl = fminf(fmaxf(ratio, 1.0f - PPO_EPS), 1.0f + PPO_EPS);
                    accClip += fminf(ratio * a, cl * a);
                    accEnt   = fmaf(pv[c], __logf(pv[c] + 1e-5f), accEnt);
                }
            }
        } else {
            int rem = T - s;
            if (rem > OUT_CHUNK) rem = OUT_CHUNK;
            for (int j = tid; j < rem; j += THREADS) {
                float p  = probs[s + j];
                float po = probs_old[s + j];
                float a  = adv[j + j / SEG];
                float ratio = __fdividef(p, po);
                float cl = fminf(fmaxf(ratio, 1.0f - PPO_EPS), 1.0f + PPO_EPS);
                accClip += fminf(ratio * a, cl * a);
                accEnt   = fmaf(p, __logf(p + 1e-5f), accEnt);
            }
        }
        __syncthreads();   // protect adv before next iteration's overwrite
    }

    // total = -accClip + C1*accVl - C2*accEnt
    float part = -accClip + PPO_C1 * accVl - PPO_C2 * accEnt;

    // ---- Block reduction (shuffle + one smem hop) ----
    #pragma unroll
    for (int off = 16; off > 0; off >>= 1)
        part += __shfl_xor_sync(0xffffffffu, part, off);
    if (lane == 0) wtg[w] = part;
    __syncthreads();
    if (w == 0) {
        float y = (lane < NWARP) ? wtg[lane] : 0.0f;
        #pragma unroll
        for (int off = NWARP / 2; off > 0; off >>= 1)
            y += __shfl_xor_sync(0xffffffffu, y, off);
        if (lane == 0) {
            g_partials[blockIdx.x] = y;
            __threadfence();
            unsigned int prev = atomicInc(&g_count, gridDim.x - 1);  // wraps to 0
            s_last = (prev == gridDim.x - 1) ? 1u : 0u;
        }
    }
    __syncthreads();

    // ---- Last block: deterministic final sum ----
    if (s_last) {
        __threadfence();
        float x = 0.0f;
        for (int i = tid; i < (int)gridDim.x; i += THREADS) x += g_partials[i];
        #pragma unroll
        for (int off = 16; off > 0; off >>= 1)
            x += __shfl_xor_sync(0xffffffffu, x, off);
        if (lane == 0) wtv[w] = x;
        __syncthreads();
        if (w == 0) {
            float y = (lane < NWARP) ? wtv[lane] : 0.0f;
            #pragma unroll
            for (int off = NWARP / 2; off > 0; off >>= 1)
                y += __shfl_xor_sync(0xffffffffu, y, off);
            if (lane == 0) out[0] = y;
        }
    }
}

extern "C" void kernel_launch(void* const* d_in, const int* in_sizes, int n_in,
                              void* d_out, int out_size)
{
    const float* probs     = (const float*)d_in[0];
    const float* probs_old = (const float*)d_in[1];
    const float* rewards   = (const float*)d_in[2];
    const float* values    = (const float*)d_in[3];
    int T = in_sizes[0];

    int nchunks = (T + OUT_CHUNK - 1) / OUT_CHUNK;   // T=2^23 -> 4096
    int grid = nchunks < GRID_MAX ? nchunks : GRID_MAX;
    if (grid > 2048) grid = 2048;                    // g_partials capacity

    ppo_fused<<<grid, THREADS>>>(probs, probs_old, rewards, values,
                                 (float*)d_out, T, nchunks);
}

// round 15
// speedup vs baseline: 1.2626x; 1.2626x over previous
#include <cuda_runtime.h>
#include <cuda_bf16.h>

// PPO loss, single fused kernel. R12 base + halo amortization: each block covers
// 4096 outputs as TWO sub-chunks processed high->low. Top sub-chunk (SEG=20,
// 2048 outputs + 512-elem halo) is exactly R12; lower sub-chunk (SEG=16, 2048
// elems, NO halo) receives the exact carry (top thread-0's final g,V) via SMEM.
// r/v overread drops 1.25x -> 1.125x (-5.4% total traffic). All register arrays
// stay phase-local (dead before each probs pass) -- the proven invariant.

#define PPO_EPS    0.2f
#define PPO_GAMMA  0.99f
#define PPO_A1     (0.99f * 0.95f)   // gamma * lambda
#define PPO_C1     0.5f
#define PPO_C2     0.01f

#define THREADS    128
#define NWARP      4
#define OUT_SUB    2048                 // outputs per sub-chunk
#define BLOCK_OUT  4096                 // two sub-chunks per block
#define SEG_TOP    20                   // top: 2560 elems (incl 512 halo)
#define SEG_LO     16                   // lower: exactly 2048 elems
#define ADV_WORDS  2176                 // max padded size (2048 + 128)

__device__ float g_partials[2048];
__device__ unsigned int g_count = 0;

__host__ __device__ constexpr double dpow(double b, int n) {
    double r = 1.0;
    for (int i = 0; i < n; ++i) r *= b;
    return r;
}

template<int SEGT, bool HAS_CARRY>
__device__ __forceinline__ void do_chunk(
    const float* __restrict__ probs, const float* __restrict__ probs_old,
    const float* __restrict__ rewards, const float* __restrict__ values,
    int s, int T,
    float* adv, float* wtg, float* wtv, float* wcg, float* wcv,
    const float* cIn, float* cOut,
    int tid, int lane, int w,
    float& accClip, float& accVl, float& accEnt)
{
    constexpr double A1d = (double)PPO_A1;
    constexpr double GVd = (double)PPO_GAMMA;
    constexpr float FG0c = (float)dpow(A1d, SEGT);          // a1^SEGT
    constexpr float FV0c = (float)dpow(GVd, SEGT);
    constexpr float FWGc = (float)dpow(A1d, SEGT * 32);     // a1^(SEGT*32)
    constexpr float FWVc = (float)dpow(GVd, SEGT * 32);
    // lane ladder a^(SEGT * 2^k)
    constexpr float LG0 = (float)dpow(A1d, SEGT),      LV0 = (float)dpow(GVd, SEGT);
    constexpr float LG1 = (float)dpow(A1d, SEGT * 2),  LV1 = (float)dpow(GVd, SEGT * 2);
    constexpr float LG2 = (float)dpow(A1d, SEGT * 4),  LV2 = (float)dpow(GVd, SEGT * 4);
    constexpr float LG3 = (float)dpow(A1d, SEGT * 8),  LV3 = (float)dpow(GVd, SEGT * 8);
    constexpr float LG4 = (float)dpow(A1d, SEGT * 16), LV4 = (float)dpow(GVd, SEGT * 16);
    // warp ladder a^(SEGT*32 * 2^k) for external-carry application
    constexpr float WG1 = (float)dpow(A1d, SEGT * 32),      WV1 = (float)dpow(GVd, SEGT * 32);
    constexpr float WG2 = (float)dpow(A1d, SEGT * 64),      WV2 = (float)dpow(GVd, SEGT * 64);

    const int gbase = s + tid * SEGT;
    const bool full = (s + OUT_SUB) <= T;

    // ---- r/v segment -> registers (critical path, issued first) ----
    float r[SEGT], v[SEGT], vNext;
    if (gbase + SEGT < T) {
        #pragma unroll
        for (int k = 0; k < SEGT / 4; ++k) {
            float4 r4 = *reinterpret_cast<const float4*>(rewards + gbase + 4 * k);
            float4 v4 = *reinterpret_cast<const float4*>(values  + gbase + 4 * k);
            r[4*k+0] = r4.x; r[4*k+1] = r4.y; r[4*k+2] = r4.z; r[4*k+3] = r4.w;
            v[4*k+0] = v4.x; v[4*k+1] = v4.y; v[4*k+2] = v4.z; v[4*k+3] = v4.w;
        }
        vNext = values[gbase + SEGT];
    } else {
        #pragma unroll
        for (int i = 0; i < SEGT; ++i) {
            bool ok = gbase + i < T;
            r[i] = ok ? rewards[gbase + i] : 0.0f;
            v[i] = ok ? values[gbase + i]  : 0.0f;
        }
        vNext = 0.0f;
    }

    // ---- L2 prefetch of this sub-chunk's probs/probs_old (after r/v issue) ----
    if (full) {
        const char* base = (tid < 64)
            ? (const char*)(probs + s)     + (size_t)tid * 128
            : (const char*)(probs_old + s) + (size_t)(tid - 64) * 128;
        asm volatile("prefetch.global.L2 [%0];" :: "l"(base));
    }

    // ---- Per-thread reverse aggregates ----
    float Lg = 0.0f, Lv = 0.0f;
    {
        float vn = vNext;
        #pragma unroll
        for (int i = SEGT - 1; i >= 0; --i) {
            float delta = r[i] - v[i] + PPO_GAMMA * vn;
            Lg = fmaf(PPO_A1,    Lg, delta);
            Lv = fmaf(PPO_GAMMA, Lv, r[i]);
            vn = v[i];
        }
    }

    // ---- Warp-level reverse inclusive scan (shfl, factor squaring) ----
    float Sg = Lg, Sv = Lv, Fg = FG0c, Fv = FV0c;
    #pragma unroll
    for (int off = 1; off < 32; off <<= 1) {
        float og = __shfl_down_sync(0xffffffffu, Sg, off);
        float ov = __shfl_down_sync(0xffffffffu, Sv, off);
        if (lane + off < 32) { Sg = fmaf(Fg, og, Sg); Sv = fmaf(Fv, ov, Sv); }
        Fg *= Fg; Fv *= Fv;
    }
    float eg = __shfl_down_sync(0xffffffffu, Sg, 1);   // within-warp carry
    float ev = __shfl_down_sync(0xffffffffu, Sv, 1);
    if (lane == 31) { eg = 0.0f; ev = 0.0f; }
    if (lane == 0) { wtg[w] = Sg; wtv[w] = Sv; }
    __syncthreads();

    // ---- Warp 0 scans the 4 warp totals ----
    if (w == 0) {
        float tg = (lane < NWARP) ? wtg[lane] : 0.0f;
        float tv = (lane < NWARP) ? wtv[lane] : 0.0f;
        float FWg = FWGc, FWv = FWVc;
        #pragma unroll
        for (int off = 1; off < NWARP; off <<= 1) {
            float og = __shfl_down_sync(0xffffffffu, tg, off);
            float ov = __shfl_down_sync(0xffffffffu, tv, off);
            if (lane + off < NWARP) { tg = fmaf(FWg, og, tg); tv = fmaf(FWv, ov, tv); }
            FWg *= FWg; FWv *= FWv;
        }
        float cg = __shfl_down_sync(0xffffffffu, tg, 1);
        float cv = __shfl_down_sync(0xffffffffu, tv, 1);
        if (lane == NWARP - 1) { cg = 0.0f; cv = 0.0f; }
        if (lane < NWARP) { wcg[lane] = cg; wcv[lane] = cv; }
    }
    __syncthreads();

    // ---- Per-thread carry: E = eg + f_lane * (wcg[w] + f_warp * C) ----
    float facg = 1.0f, facv = 1.0f;
    {
        int m = 31 - lane;
        if (m & 1)  { facg *= LG0; facv *= LV0; }
        if (m & 2)  { facg *= LG1; facv *= LV1; }
        if (m & 4)  { facg *= LG2; facv *= LV2; }
        if (m & 8)  { facg *= LG3; facv *= LV3; }
        if (m & 16) { facg *= LG4; facv *= LV4; }
    }
    float Cg = 0.0f, Cv = 0.0f;
    if (HAS_CARRY) { Cg = cIn[0]; Cv = cIn[1]; }
    float wfg = 1.0f, wfv = 1.0f;
    {
        int j = NWARP - 1 - w;
        if (j & 1) { wfg *= WG1; wfv *= WV1; }
        if (j & 2) { wfg *= WG2; wfv *= WV2; }
    }
    float Eg = fmaf(facg, fmaf(wfg, Cg, wcg[w]), eg);
    float Ev = fmaf(facv, fmaf(wfv, Cv, wcv[w]), ev);

    // ---- Recompute with carry: value loss + adv -> SMEM (LAST use of r/v) ----
    const int baseL = tid * SEGT;
    const int baseP = baseL + tid;   // (SEGT+1)*tid padded layout
    {
        float g = Eg, V = Ev, vn = vNext;
        #pragma unroll
        for (int i = SEGT - 1; i >= 0; --i) {
            float delta = r[i] - v[i] + PPO_GAMMA * vn;
            g = fmaf(PPO_A1,    g, delta);
            V = fmaf(PPO_GAMMA, V, r[i]);
            vn = v[i];
            if (baseL + i < OUT_SUB) {
                float d = v[i] - V;
                accVl = fmaf(d, d, accVl);
                adv[baseP + i] = g;
            }
        }
        if (tid == 0) { cOut[0] = g; cOut[1] = V; }   // exact carry at element s
    }
    __syncthreads();   // adv + carry visible

    // ---- Coalesced probs pass (L2-hit after prefetch) ----
    if (full) {
        const float4* p4p  = reinterpret_cast<const float4*>(probs + s);
        const float4* po4p = reinterpret_cast<const float4*>(probs_old + s);
        #pragma unroll
        for (int it = 0; it < OUT_SUB / (4 * THREADS); ++it) {   // 4 iters
            int k = tid + it * THREADS;
            float4 p4 = p4p[k];
            float4 o4 = po4p[k];
            float pv[4] = {p4.x, p4.y, p4.z, p4.w};
            float ov[4] = {o4.x, o4.y, o4.z, o4.w};
            int li = 4 * k;
            #pragma unroll
            for (int c = 0; c < 4; ++c) {
                int j = li + c;
                float a = adv[j + j / SEGT];
                float ratio = __fdividef(pv[c], ov[c]);
                float cl = fminf(fmaxf(ratio, 1.0f - PPO_EPS), 1.0f + PPO_EPS);
                accClip += fminf(ratio * a, cl * a);
                accEnt   = fmaf(pv[c], __logf(pv[c] + 1e-5f), accEnt);
            }
        }
    } else {
        int rem = T - s;
        if (rem < 0) rem = 0;
        if (rem > OUT_SUB) rem = OUT_SUB;
        for (int j = tid; j < rem; j += THREADS) {
            float p  = probs[s + j];
            float po = probs_old[s + j];
            float a  = adv[j + j / SEGT];
            float ratio = __fdividef(p, po);
            float cl = fminf(fmaxf(ratio, 1.0f - PPO_EPS), 1.0f + PPO_EPS);
            accClip += fminf(ratio * a, cl * a);
            accEnt   = fmaf(p, __logf(p + 1e-5f), accEnt);
        }
    }
    __syncthreads();   // protect adv/carry before next sub-chunk
}

__global__ __launch_bounds__(THREADS, 8)
void ppo_fused(const float* __restrict__ probs,
               const float* __restrict__ probs_old,
               const float* __restrict__ rewards,
               const float* __restrict__ values,
               float* __restrict__ out,
               int T)
{
    __shared__ float adv[ADV_WORDS];
    __shared__ float wtg[NWARP], wtv[NWARP];
    __shared__ float wcg[NWARP], wcv[NWARP];
    __shared__ float cTop[2], cDead[2];
    __shared__ unsigned int s_last;

    const int tid  = threadIdx.x;
    const int lane = tid & 31;
    const int w    = tid >> 5;
    const int B = blockIdx.x * BLOCK_OUT;

    float accClip = 0.0f, accVl = 0.0f, accEnt = 0.0f;

    // Top sub-chunk: [B+2048, B+4096) outputs, 512-elem halo, no carry-in.
    do_chunk<SEG_TOP, false>(probs, probs_old, rewards, values,
                             B + OUT_SUB, T,
                             adv, wtg, wtv, wcg, wcv,
                             nullptr, cTop,
                             tid, lane, w, accClip, accVl, accEnt);
    // Lower sub-chunk: [B, B+2048), exact carry from top, no halo.
    do_chunk<SEG_LO, true>(probs, probs_old, rewards, values,
                           B, T,
                           adv, wtg, wtv, wcg, wcv,
                           cTop, cDead,
                           tid, lane, w, accClip, accVl, accEnt);

    // total = -accClip + C1*accVl - C2*accEnt
    float part = -accClip + PPO_C1 * accVl - PPO_C2 * accEnt;

    // ---- Block reduction (shuffle + one smem hop) ----
    #pragma unroll
    for (int off = 16; off > 0; off >>= 1)
        part += __shfl_xor_sync(0xffffffffu, part, off);
    if (lane == 0) wtg[w] = part;
    __syncthreads();
    if (w == 0) {
        float y = (lane < NWARP) ? wtg[lane] : 0.0f;
        #pragma unroll
        for (int off = NWARP / 2; off > 0; off >>= 1)
            y += __shfl_xor_sync(0xffffffffu, y, off);
        if (lane == 0) {
            g_partials[blockIdx.x] = y;
            __threadfence();
            unsigned int prev = atomicInc(&g_count, gridDim.x - 1);  // wraps to 0
            s_last = (prev == gridDim.x - 1) ? 1u : 0u;
        }
    }
    __syncthreads();

    // ---- Last block: deterministic final sum ----
    if (s_last) {
        __threadfence();
        float x = 0.0f;
        for (int i = tid; i < (int)gridDim.x; i += THREADS) x += g_partials[i];
        #pragma unroll
        for (int off = 16; off > 0; off >>= 1)
            x += __shfl_xor_sync(0xffffffffu, x, off);
        if (lane == 0) wtv[w] = x;
        __syncthreads();
        if (w == 0) {
            float y = (lane < NWARP) ? wtv[lane] : 0.0f;
            #pragma unroll
            for (int off = NWARP / 2; off > 0; off >>= 1)
                y += __shfl_xor_sync(0xffffffffu, y, off);
            if (lane == 0) out[0] = y;
        }
    }
}

extern "C" void kernel_launch(void* const* d_in, const int* in_sizes, int n_in,
                              void* d_out, int out_size)
{
    const float* probs     = (const float*)d_in[0];
    const float* probs_old = (const float*)d_in[1];
    const float* rewards   = (const float*)d_in[2];
    const float* values    = (const float*)d_in[3];
    int T = in_sizes[0];

    int nblocks = (T + BLOCK_OUT - 1) / BLOCK_OUT;   // T=2^23 -> 2048
    if (nblocks > 2048) nblocks = 2048;              // g_partials capacity

    ppo_fused<<<nblocks, THREADS>>>(probs, probs_old, rewards, values,
                                    (float*)d_out, T);
}